// round 8
// baseline (speedup 1.0000x reference)
#include <cuda_runtime.h>
#include <math.h>
#include <stdint.h>

#define NNODES 50000
#define NEDGES 600000
#define DD 128
#define NGRAPHS 512
#define NCLASSES 10
#define NLAYERS 4

// ---------------- scratch (static device globals) ---------------------------
__device__ float d_h[NNODES * DD];
__device__ float d_m[NNODES * DD];
__device__ float d_gi[NNODES * 3 * DD];
__device__ float d_gh[NNODES * 3 * DD];
// pre-split tf32 hi/lo operand arrays (fp32 bitpatterns, tf32-rounded)
__device__ float d_h_hi[NNODES * DD];
__device__ float d_h_lo[NNODES * DD];
__device__ float d_agg_hi[NNODES * DD];
__device__ float d_agg_lo[NNODES * DD];
__device__ float d_wB1_hi[NLAYERS * 512 * DD];   // [Whh(384) ; Ws^T(128)]
__device__ float d_wB1_lo[NLAYERS * 512 * DD];
__device__ float d_wih_hi[NLAYERS * 384 * DD];
__device__ float d_wih_lo[NLAYERS * 384 * DD];
__device__ int   d_off[NNODES + 1];
__device__ int   d_cnt[NNODES];
__device__ int   d_csc[NEDGES];
__device__ float d_pool[NGRAPHS * DD];
__device__ float d_gcnt[NGRAPHS];
__device__ float d_logits[NGRAPHS * NCLASSES];
__device__ int   d_is64;

// ---------------- tf32 helpers ------------------------------------------------
__device__ __forceinline__ uint32_t f2tf32(float x) {
    uint32_t r;
    asm("cvt.rna.tf32.f32 %0, %1;" : "=r"(r) : "f"(x));
    return r;
}
__device__ __forceinline__ void split_store(float x, float* hi, float* lo) {
    uint32_t h = f2tf32(x);
    *hi = __uint_as_float(h);
    *lo = __uint_as_float(f2tf32(x - __uint_as_float(h)));
}
__device__ __forceinline__ void mma_tf32(float* c, const uint32_t* a, const uint32_t* b) {
    asm volatile(
        "mma.sync.aligned.m16n8k8.row.col.f32.tf32.tf32.f32 "
        "{%0,%1,%2,%3},{%4,%5,%6,%7},{%8,%9},{%0,%1,%2,%3};"
        : "+f"(c[0]), "+f"(c[1]), "+f"(c[2]), "+f"(c[3])
        : "r"(a[0]), "r"(a[1]), "r"(a[2]), "r"(a[3]), "r"(b[0]), "r"(b[1]));
}

// ---------------- index dtype detection ---------------------------------------
__global__ void detect_kernel(const void* __restrict__ ei) {
    __shared__ int nz;
    if (threadIdx.x == 0) nz = 0;
    __syncthreads();
    const int* w = (const int*)ei;
    int v = w[2 * threadIdx.x + 1];
    if (v != 0) atomicAdd(&nz, 1);
    __syncthreads();
    if (threadIdx.x == 0) d_is64 = (nz == 0) ? 1 : 0;
}
__device__ __forceinline__ int load_idx(const void* p, int i) {
    return d_is64 ? (int)((const long long*)p)[i] : ((const int*)p)[i];
}

// ---------------- utility kernels ---------------------------------------------
__global__ void copy_h_kernel(const float* __restrict__ src, int n) {
    int i = blockIdx.x * blockDim.x + threadIdx.x;
    if (i < n) {
        float x = src[i];
        d_h[i] = x;
        split_store(x, &d_h_hi[i], &d_h_lo[i]);
    }
}
__global__ void zero_cnt_kernel(int n) {
    int i = blockIdx.x * blockDim.x + threadIdx.x;
    if (i < n) d_cnt[i] = 0;
}
__global__ void zero_pool_kernel() {
    int i = blockIdx.x * blockDim.x + threadIdx.x;
    if (i < NGRAPHS * DD) d_pool[i] = 0.f;
    if (i < NGRAPHS) d_gcnt[i] = 0.f;
}
// B1 = [Whh (rows 0..383) ; Ws^T (rows 384..511)] per layer, pre-split
__global__ void conv_wB1_kernel(const float* __restrict__ Whh, const float* __restrict__ Ws) {
    int i = blockIdx.x * blockDim.x + threadIdx.x;
    if (i >= NLAYERS * 512 * DD) return;
    int l = i / (512 * DD);
    int r = (i / DD) % 512;
    int k = i % DD;
    float x = (r < 384) ? Whh[(size_t)l * 384 * DD + r * DD + k]
                        : Ws[(size_t)l * DD * DD + k * DD + (r - 384)];
    split_store(x, &d_wB1_hi[i], &d_wB1_lo[i]);
}
__global__ void conv_wih_kernel(const float* __restrict__ Wih) {
    int i = blockIdx.x * blockDim.x + threadIdx.x;
    if (i >= NLAYERS * 384 * DD) return;
    split_store(Wih[i], &d_wih_hi[i], &d_wih_lo[i]);
}

// ---------------- CSC build ----------------------------------------------------
__global__ void count_kernel(const void* __restrict__ ei, int n_edges) {
    int e = blockIdx.x * blockDim.x + threadIdx.x;
    if (e >= n_edges) return;
    int dst = load_idx(ei, n_edges + e);
    if (dst >= 0 && dst < NNODES) atomicAdd(&d_cnt[dst], 1);
}
__global__ void scan_kernel(int n) {
    __shared__ int tmp[1024];
    __shared__ int carry;
    int tid = threadIdx.x;
    if (tid == 0) carry = 0;
    __syncthreads();
    for (int base = 0; base < n; base += 1024) {
        int v = (base + tid < n) ? d_cnt[base + tid] : 0;
        tmp[tid] = v;
        __syncthreads();
        for (int off = 1; off < 1024; off <<= 1) {
            int t = (tid >= off) ? tmp[tid - off] : 0;
            __syncthreads();
            tmp[tid] += t;
            __syncthreads();
        }
        int excl = tmp[tid] - v;
        if (base + tid < n) d_off[base + tid] = carry + excl;
        __syncthreads();
        if (tid == 1023) carry += tmp[1023];
        __syncthreads();
    }
    if (tid == 0) d_off[n] = carry;
}
__global__ void fill_kernel(const void* __restrict__ ei, int n_edges) {
    int e = blockIdx.x * blockDim.x + threadIdx.x;
    if (e >= n_edges) return;
    int dst = load_idx(ei, n_edges + e);
    int src = load_idx(ei, e);
    if (dst < 0 || dst >= NNODES || src < 0 || src >= NNODES) return;
    int pos = d_off[dst] + atomicAdd(&d_cnt[dst], 1);
    if (pos < NEDGES) d_csc[pos] = src;
}

// ---------------- aggregation: one warp per node; emits tf32 hi/lo -------------
__global__ void agg_kernel(int n_nodes) {
    int warp = (blockIdx.x * blockDim.x + threadIdx.x) >> 5;
    int lane = threadIdx.x & 31;
    if (warp >= n_nodes) return;
    int s = d_off[warp], e = d_off[warp + 1];
    float4 acc = make_float4(0.f, 0.f, 0.f, 0.f);
    for (int i = s; i < e; i++) {
        int src = d_csc[i];
        float4 v = *(const float4*)(d_m + (size_t)src * DD + lane * 4);
        acc.x += v.x; acc.y += v.y; acc.z += v.z; acc.w += v.w;
    }
    int base = warp * DD + lane * 4;
    float4 hi, lo;
    split_store(acc.x, &hi.x, &lo.x);
    split_store(acc.y, &hi.y, &lo.y);
    split_store(acc.z, &hi.z, &lo.z);
    split_store(acc.w, &hi.w, &lo.w);
    *(float4*)&d_agg_hi[base] = hi;
    *(float4*)&d_agg_lo[base] = lo;
}

// ---------------- tf32x3 tensor-core GEMM (pre-split operands) -----------------
// C[M,:] = (Ahi+Alo)[M,128] @ (Bhi+Blo)[N,128]^T (+bias)
// cols < N1 -> C1 (stride N1), else C2 (stride 128).
#define SAW 36
__device__ __forceinline__ void gemm_tf32_body(
    const float* __restrict__ Ahi, const float* __restrict__ Alo,
    const float* __restrict__ Bhi, const float* __restrict__ Blo,
    const float* __restrict__ bias, float* __restrict__ C1, int N1,
    float* __restrict__ C2, int M)
{
    __shared__ float sAh[128][SAW], sAl[128][SAW];
    __shared__ float sBh[64][SAW], sBl[64][SAW];
    int tid = threadIdx.x, lane = tid & 31, wid = tid >> 5;
    int g = lane >> 2, tg = lane & 3;
    int m0 = blockIdx.x * 128, n0 = blockIdx.y * 64;
    int wm0 = (wid & 3) * 32, wn0 = (wid >> 2) * 32;

    float c[2][4][4] = {};

    for (int k0 = 0; k0 < 128; k0 += 32) {
#pragma unroll
        for (int t = 0; t < 4; t++) {
            int ch = tid + t * 256;
            int row = ch >> 3, q = ch & 7;
            float4 vh = make_float4(0.f, 0.f, 0.f, 0.f);
            float4 vl = make_float4(0.f, 0.f, 0.f, 0.f);
            int gr = m0 + row;
            if (gr < M) {
                vh = *(const float4*)&Ahi[(size_t)gr * 128 + k0 + q * 4];
                vl = *(const float4*)&Alo[(size_t)gr * 128 + k0 + q * 4];
            }
            *(float4*)&sAh[row][q * 4] = vh;
            *(float4*)&sAl[row][q * 4] = vl;
        }
#pragma unroll
        for (int t = 0; t < 2; t++) {
            int ch = tid + t * 256;
            int row = ch >> 3, q = ch & 7;
            *(float4*)&sBh[row][q * 4] = *(const float4*)&Bhi[(size_t)(n0 + row) * 128 + k0 + q * 4];
            *(float4*)&sBl[row][q * 4] = *(const float4*)&Blo[(size_t)(n0 + row) * 128 + k0 + q * 4];
        }
        __syncthreads();

#pragma unroll
        for (int ks = 0; ks < 32; ks += 8) {
            // m16n8k8 tf32 fragments:
            //  a0=A[g][tg] a1=A[g+8][tg] a2=A[g][tg+4] a3=A[g+8][tg+4]
            //  b0=B[tg][g] b1=B[tg+4][g]  (B stored [n][k])
            uint32_t ahi[2][4], alo[2][4], bhi[4][2], blo[4][2];
#pragma unroll
            for (int mt = 0; mt < 2; mt++) {
                int r0 = wm0 + mt * 16 + g;
                ahi[mt][0] = __float_as_uint(sAh[r0][ks + tg]);
                ahi[mt][1] = __float_as_uint(sAh[r0 + 8][ks + tg]);
                ahi[mt][2] = __float_as_uint(sAh[r0][ks + tg + 4]);
                ahi[mt][3] = __float_as_uint(sAh[r0 + 8][ks + tg + 4]);
                alo[mt][0] = __float_as_uint(sAl[r0][ks + tg]);
                alo[mt][1] = __float_as_uint(sAl[r0 + 8][ks + tg]);
                alo[mt][2] = __float_as_uint(sAl[r0][ks + tg + 4]);
                alo[mt][3] = __float_as_uint(sAl[r0 + 8][ks + tg + 4]);
            }
#pragma unroll
            for (int nt = 0; nt < 4; nt++) {
                int r = wn0 + nt * 8 + g;
                bhi[nt][0] = __float_as_uint(sBh[r][ks + tg]);
                bhi[nt][1] = __float_as_uint(sBh[r][ks + tg + 4]);
                blo[nt][0] = __float_as_uint(sBl[r][ks + tg]);
                blo[nt][1] = __float_as_uint(sBl[r][ks + tg + 4]);
            }
#pragma unroll
            for (int mt = 0; mt < 2; mt++)
#pragma unroll
                for (int nt = 0; nt < 4; nt++) {
                    mma_tf32(c[mt][nt], ahi[mt], bhi[nt]);
                    mma_tf32(c[mt][nt], ahi[mt], blo[nt]);
                    mma_tf32(c[mt][nt], alo[mt], bhi[nt]);
                }
        }
        __syncthreads();
    }

#pragma unroll
    for (int mt = 0; mt < 2; mt++)
#pragma unroll
        for (int nt = 0; nt < 4; nt++)
#pragma unroll
            for (int hr = 0; hr < 2; hr++) {
                int row = m0 + wm0 + mt * 16 + g + hr * 8;
                if (row >= M) continue;
                int col = n0 + wn0 + nt * 8 + tg * 2;
                float v0 = c[mt][nt][hr * 2 + 0];
                float v1 = c[mt][nt][hr * 2 + 1];
                if (col < N1) {
                    if (bias) { v0 += bias[col]; v1 += bias[col + 1]; }
                    *(float2*)&C1[(size_t)row * N1 + col] = make_float2(v0, v1);
                } else {
                    *(float2*)&C2[(size_t)row * DD + (col - N1)] = make_float2(v0, v1);
                }
            }
}

// fused: [gh | m] = h @ [Whh^T | Ws]
__global__ __launch_bounds__(256) void gemm1_kernel(const float* __restrict__ bhh, int l, int M) {
    gemm_tf32_body(d_h_hi, d_h_lo,
                   d_wB1_hi + (size_t)l * 512 * DD, d_wB1_lo + (size_t)l * 512 * DD,
                   bhh, d_gh, 384, d_m, M);
}
// gi = agg @ Wih^T + bih
__global__ __launch_bounds__(256) void gemm2_kernel(const float* __restrict__ bih, int l, int M) {
    gemm_tf32_body(d_agg_hi, d_agg_lo,
                   d_wih_hi + (size_t)l * 384 * DD, d_wih_lo + (size_t)l * 384 * DD,
                   bih, d_gi, 384, nullptr, M);
}

// ---------------- fused GRU gates + ReLU; emits tf32 hi/lo ---------------------
__global__ void gru_kernel(int n_nodes) {
    int idx = blockIdx.x * blockDim.x + threadIdx.x;
    if (idx >= n_nodes * DD) return;
    int i = idx / DD, j = idx % DD;
    const float* gir = d_gi + (size_t)i * 3 * DD;
    const float* ghr = d_gh + (size_t)i * 3 * DD;
    float ir = gir[j], iz = gir[DD + j], in_ = gir[2 * DD + j];
    float hr = ghr[j], hz = ghr[DD + j], hn = ghr[2 * DD + j];
    float r = 1.f / (1.f + expf(-(ir + hr)));
    float z = 1.f / (1.f + expf(-(iz + hz)));
    float nn = tanhf(in_ + r * hn);
    float hv = d_h[idx];
    float out = fmaxf((1.f - z) * nn + z * hv, 0.f);
    d_h[idx] = out;
    split_store(out, &d_h_hi[idx], &d_h_lo[idx]);
}

// ---------------- mean pool -----------------------------------------------------
__global__ void pool_kernel(const void* __restrict__ batch, int n_nodes) {
    int idx = blockIdx.x * blockDim.x + threadIdx.x;
    if (idx >= n_nodes * DD) return;
    int i = idx / DD, j = idx % DD;
    int g = load_idx(batch, i);
    if (g < 0 || g >= NGRAPHS) return;
    atomicAdd(&d_pool[g * DD + j], d_h[idx]);
    if (j == 0) atomicAdd(&d_gcnt[g], 1.f);
}

// ---------------- readout FC1(elu) + FC2 ----------------------------------------
__global__ void readout_kernel(const float* __restrict__ fc1w, const float* __restrict__ fc1b,
                               const float* __restrict__ fc2w, const float* __restrict__ fc2b) {
    int g = blockIdx.x;
    int j = threadIdx.x;
    __shared__ float hg[DD];
    __shared__ float h2[DD];
    float c = fmaxf(d_gcnt[g], 1.f);
    hg[j] = d_pool[g * DD + j] / c;
    __syncthreads();
    float a = fc1b[j];
#pragma unroll 4
    for (int k = 0; k < DD; k++) a += hg[k] * fc1w[j * DD + k];
    h2[j] = (a > 0.f) ? a : expm1f(a);
    __syncthreads();
    if (j < NCLASSES) {
        float s = fc2b[j];
#pragma unroll 4
        for (int k = 0; k < DD; k++) s += h2[k] * fc2w[j * DD + k];
        d_logits[g * NCLASSES + j] = s;
    }
}

// ---------------- log_softmax over axis 0 ---------------------------------------
__global__ void lsm_kernel(float* __restrict__ out) {
    int c = blockIdx.x;
    int g = threadIdx.x;
    __shared__ float sh[NGRAPHS];
    float x = d_logits[g * NCLASSES + c];
    sh[g] = x;
    __syncthreads();
    for (int off = NGRAPHS / 2; off > 0; off >>= 1) {
        if (g < off) sh[g] = fmaxf(sh[g], sh[g + off]);
        __syncthreads();
    }
    float mx = sh[0];
    __syncthreads();
    sh[g] = expf(x - mx);
    __syncthreads();
    for (int off = NGRAPHS / 2; off > 0; off >>= 1) {
        if (g < off) sh[g] += sh[g + off];
        __syncthreads();
    }
    float lse = mx + logf(sh[0]);
    out[g * NCLASSES + c] = x - lse;
}

// ---------------- launch ---------------------------------------------------------
extern "C" void kernel_launch(void* const* d_in, const int* in_sizes, int n_in,
                              void* d_out, int out_size) {
    const float* h_in  = (const float*)d_in[0];
    const void*  ei    = d_in[1];
    const void*  batch = d_in[3];
    const float* Ws   = (const float*)d_in[4];
    const float* Wih  = (const float*)d_in[5];
    const float* Whh  = (const float*)d_in[6];
    const float* bih  = (const float*)d_in[7];
    const float* bhh  = (const float*)d_in[8];
    const float* fc1w = (const float*)d_in[9];
    const float* fc1b = (const float*)d_in[10];
    const float* fc2w = (const float*)d_in[11];
    const float* fc2b = (const float*)d_in[12];
    float* out = (float*)d_out;

    int n_nodes = in_sizes[0] / DD;
    int n_edges = in_sizes[1] / 2;
    int nh = n_nodes * DD;

    detect_kernel<<<1, 128>>>(ei);
    copy_h_kernel<<<(nh + 255) / 256, 256>>>(h_in, nh);
    conv_wB1_kernel<<<(NLAYERS * 512 * DD + 255) / 256, 256>>>(Whh, Ws);
    conv_wih_kernel<<<(NLAYERS * 384 * DD + 255) / 256, 256>>>(Wih);

    // CSC build (once; reused across layers)
    zero_cnt_kernel<<<(n_nodes + 255) / 256, 256>>>(n_nodes);
    count_kernel<<<(n_edges + 255) / 256, 256>>>(ei, n_edges);
    scan_kernel<<<1, 1024>>>(n_nodes);
    zero_cnt_kernel<<<(n_nodes + 255) / 256, 256>>>(n_nodes);
    fill_kernel<<<(n_edges + 255) / 256, 256>>>(ei, n_edges);

    dim3 grid1((n_nodes + 127) / 128, 8);   // 512 output cols: [gh(384) | m(128)]
    dim3 grid2((n_nodes + 127) / 128, 6);   // 384 output cols: gi

    for (int l = 0; l < NLAYERS; l++) {
        gemm1_kernel<<<grid1, 256>>>(bhh + (size_t)l * 3 * DD, l, n_nodes);
        agg_kernel<<<(n_nodes * 32 + 255) / 256, 256>>>(n_nodes);
        gemm2_kernel<<<grid2, 256>>>(bih + (size_t)l * 3 * DD, l, n_nodes);
        gru_kernel<<<(nh + 255) / 256, 256>>>(n_nodes);
    }

    zero_pool_kernel<<<(NGRAPHS * DD + 255) / 256, 256>>>();
    pool_kernel<<<(nh + 255) / 256, 256>>>(batch, n_nodes);
    readout_kernel<<<NGRAPHS, DD>>>(fc1w, fc1b, fc2w, fc2b);
    lsm_kernel<<<NCLASSES, NGRAPHS>>>(out);
}

// round 9
// speedup vs baseline: 1.0845x; 1.0845x over previous
#include <cuda_runtime.h>
#include <math.h>
#include <stdint.h>

#define NNODES 50000
#define NEDGES 600000
#define DD 128
#define NGRAPHS 512
#define NCLASSES 10
#define NLAYERS 4

// ---------------- scratch (static device globals) ---------------------------
__device__ float d_h[NNODES * DD];
__device__ float d_m[NNODES * DD];
__device__ float d_agg[NNODES * DD];
__device__ float d_gi[NNODES * 3 * DD];
__device__ float d_gh[NNODES * 3 * DD];
__device__ float d_wB1[NLAYERS * 512 * DD];   // [Whh(384) ; Ws^T(128)] per layer
__device__ int   d_off[NNODES + 1];
__device__ int   d_cnt[NNODES];
__device__ int   d_csc[NEDGES];
__device__ float d_pool[NGRAPHS * DD];
__device__ float d_gcnt[NGRAPHS];
__device__ float d_logits[NGRAPHS * NCLASSES];
__device__ int   d_is64;

// ---------------- tf32 helpers ------------------------------------------------
__device__ __forceinline__ uint32_t f2tf32(float x) {
    uint32_t r;
    asm("cvt.rna.tf32.f32 %0, %1;" : "=r"(r) : "f"(x));
    return r;
}
__device__ __forceinline__ void split2(float x, float& hi, float& lo) {
    uint32_t h = f2tf32(x);
    hi = __uint_as_float(h);
    lo = __uint_as_float(f2tf32(x - __uint_as_float(h)));
}
__device__ __forceinline__ void mma_tf32(float* c, const uint32_t* a, const uint32_t* b) {
    asm volatile(
        "mma.sync.aligned.m16n8k8.row.col.f32.tf32.tf32.f32 "
        "{%0,%1,%2,%3},{%4,%5,%6,%7},{%8,%9},{%0,%1,%2,%3};"
        : "+f"(c[0]), "+f"(c[1]), "+f"(c[2]), "+f"(c[3])
        : "r"(a[0]), "r"(a[1]), "r"(a[2]), "r"(a[3]), "r"(b[0]), "r"(b[1]));
}

// ---------------- index dtype detection ---------------------------------------
__global__ void detect_kernel(const void* __restrict__ ei) {
    __shared__ int nz;
    if (threadIdx.x == 0) nz = 0;
    __syncthreads();
    const int* w = (const int*)ei;
    int v = w[2 * threadIdx.x + 1];
    if (v != 0) atomicAdd(&nz, 1);
    __syncthreads();
    if (threadIdx.x == 0) d_is64 = (nz == 0) ? 1 : 0;
}
__device__ __forceinline__ int load_idx(const void* p, int i) {
    return d_is64 ? (int)((const long long*)p)[i] : ((const int*)p)[i];
}

// ---------------- utility kernels ---------------------------------------------
__global__ void copy_h_kernel(const float* __restrict__ src, int n) {
    int i = blockIdx.x * blockDim.x + threadIdx.x;
    if (i < n) d_h[i] = src[i];
}
__global__ void zero_cnt_kernel(int n) {
    int i = blockIdx.x * blockDim.x + threadIdx.x;
    if (i < n) d_cnt[i] = 0;
}
__global__ void zero_pool_kernel() {
    int i = blockIdx.x * blockDim.x + threadIdx.x;
    if (i < NGRAPHS * DD) d_pool[i] = 0.f;
    if (i < NGRAPHS) d_gcnt[i] = 0.f;
}
// B1 = [Whh (rows 0..383) ; Ws^T (rows 384..511)] per layer, fp32
__global__ void conv_wB1_kernel(const float* __restrict__ Whh, const float* __restrict__ Ws) {
    int i = blockIdx.x * blockDim.x + threadIdx.x;
    if (i >= NLAYERS * 512 * DD) return;
    int l = i / (512 * DD);
    int r = (i / DD) % 512;
    int k = i % DD;
    d_wB1[i] = (r < 384) ? Whh[(size_t)l * 384 * DD + r * DD + k]
                         : Ws[(size_t)l * DD * DD + k * DD + (r - 384)];
}

// ---------------- CSC build ----------------------------------------------------
__global__ void count_kernel(const void* __restrict__ ei, int n_edges) {
    int e = blockIdx.x * blockDim.x + threadIdx.x;
    if (e >= n_edges) return;
    int dst = load_idx(ei, n_edges + e);
    if (dst >= 0 && dst < NNODES) atomicAdd(&d_cnt[dst], 1);
}
__global__ void scan_kernel(int n) {
    __shared__ int tmp[1024];
    __shared__ int carry;
    int tid = threadIdx.x;
    if (tid == 0) carry = 0;
    __syncthreads();
    for (int base = 0; base < n; base += 1024) {
        int v = (base + tid < n) ? d_cnt[base + tid] : 0;
        tmp[tid] = v;
        __syncthreads();
        for (int off = 1; off < 1024; off <<= 1) {
            int t = (tid >= off) ? tmp[tid - off] : 0;
            __syncthreads();
            tmp[tid] += t;
            __syncthreads();
        }
        int excl = tmp[tid] - v;
        if (base + tid < n) d_off[base + tid] = carry + excl;
        __syncthreads();
        if (tid == 1023) carry += tmp[1023];
        __syncthreads();
    }
    if (tid == 0) d_off[n] = carry;
}
__global__ void fill_kernel(const void* __restrict__ ei, int n_edges) {
    int e = blockIdx.x * blockDim.x + threadIdx.x;
    if (e >= n_edges) return;
    int dst = load_idx(ei, n_edges + e);
    int src = load_idx(ei, e);
    if (dst < 0 || dst >= NNODES || src < 0 || src >= NNODES) return;
    int pos = d_off[dst] + atomicAdd(&d_cnt[dst], 1);
    if (pos < NEDGES) d_csc[pos] = src;
}

// ---------------- aggregation: one warp per node, float4 per lane --------------
__global__ void agg_kernel(int n_nodes) {
    int warp = (blockIdx.x * blockDim.x + threadIdx.x) >> 5;
    int lane = threadIdx.x & 31;
    if (warp >= n_nodes) return;
    int s = d_off[warp], e = d_off[warp + 1];
    float4 acc = make_float4(0.f, 0.f, 0.f, 0.f);
    for (int i = s; i < e; i++) {
        int src = d_csc[i];
        float4 v = *(const float4*)(d_m + (size_t)src * DD + lane * 4);
        acc.x += v.x; acc.y += v.y; acc.z += v.z; acc.w += v.w;
    }
    *(float4*)(d_agg + (size_t)warp * DD + lane * 4) = acc;
}

// ---------------- tf32x3 GEMM: split at staging, BK=16 chunks ------------------
// C[M,:] = A[M,128] @ B[N,128]^T (+bias); cols < N1 -> C1, else C2 (stride 128).
#define SW 20   // padded row width for 16-col chunk; (20g+tg) mod 32 conflict-free
__device__ __forceinline__ void gemm_tf32_body(
    const float* __restrict__ A, const float* __restrict__ B,
    const float* __restrict__ bias, float* __restrict__ C1, int N1,
    float* __restrict__ C2, int M)
{
    __shared__ float sAh[128][SW], sAl[128][SW];
    __shared__ float sBh[64][SW], sBl[64][SW];
    int tid = threadIdx.x, lane = tid & 31, wid = tid >> 5;
    int g = lane >> 2, tg = lane & 3;
    int m0 = blockIdx.x * 128, n0 = blockIdx.y * 64;
    int wm0 = (wid & 3) * 32, wn0 = (wid >> 2) * 32;

    float c[2][4][4] = {};

    for (int k0 = 0; k0 < 128; k0 += 16) {
        // stage A chunk 128x16: 512 float4 = 2 per thread; split -> hi/lo smem
#pragma unroll
        for (int t = 0; t < 2; t++) {
            int ch = tid + t * 256;
            int row = ch >> 2, q = ch & 3;
            float4 v = make_float4(0.f, 0.f, 0.f, 0.f);
            int gr = m0 + row;
            if (gr < M) v = *(const float4*)&A[(size_t)gr * 128 + k0 + q * 4];
            float4 hi, lo;
            split2(v.x, hi.x, lo.x);
            split2(v.y, hi.y, lo.y);
            split2(v.z, hi.z, lo.z);
            split2(v.w, hi.w, lo.w);
            *(float4*)&sAh[row][q * 4] = hi;
            *(float4*)&sAl[row][q * 4] = lo;
        }
        // stage B chunk 64x16: 256 float4 = 1 per thread
        {
            int row = tid >> 2, q = tid & 3;
            float4 v = *(const float4*)&B[(size_t)(n0 + row) * 128 + k0 + q * 4];
            float4 hi, lo;
            split2(v.x, hi.x, lo.x);
            split2(v.y, hi.y, lo.y);
            split2(v.z, hi.z, lo.z);
            split2(v.w, hi.w, lo.w);
            *(float4*)&sBh[row][q * 4] = hi;
            *(float4*)&sBl[row][q * 4] = lo;
        }
        __syncthreads();

#pragma unroll
        for (int ks = 0; ks < 16; ks += 8) {
            // m16n8k8 tf32 fragments:
            //  a0=A[g][tg] a1=A[g+8][tg] a2=A[g][tg+4] a3=A[g+8][tg+4]
            //  b0=B[tg][g] b1=B[tg+4][g]  (B stored [n][k])
            uint32_t ahi[2][4], alo[2][4], bhi[4][2], blo[4][2];
#pragma unroll
            for (int mt = 0; mt < 2; mt++) {
                int r0 = wm0 + mt * 16 + g;
                ahi[mt][0] = __float_as_uint(sAh[r0][ks + tg]);
                ahi[mt][1] = __float_as_uint(sAh[r0 + 8][ks + tg]);
                ahi[mt][2] = __float_as_uint(sAh[r0][ks + tg + 4]);
                ahi[mt][3] = __float_as_uint(sAh[r0 + 8][ks + tg + 4]);
                alo[mt][0] = __float_as_uint(sAl[r0][ks + tg]);
                alo[mt][1] = __float_as_uint(sAl[r0 + 8][ks + tg]);
                alo[mt][2] = __float_as_uint(sAl[r0][ks + tg + 4]);
                alo[mt][3] = __float_as_uint(sAl[r0 + 8][ks + tg + 4]);
            }
#pragma unroll
            for (int nt = 0; nt < 4; nt++) {
                int r = wn0 + nt * 8 + g;
                bhi[nt][0] = __float_as_uint(sBh[r][ks + tg]);
                bhi[nt][1] = __float_as_uint(sBh[r][ks + tg + 4]);
                blo[nt][0] = __float_as_uint(sBl[r][ks + tg]);
                blo[nt][1] = __float_as_uint(sBl[r][ks + tg + 4]);
            }
#pragma unroll
            for (int mt = 0; mt < 2; mt++)
#pragma unroll
                for (int nt = 0; nt < 4; nt++) {
                    mma_tf32(c[mt][nt], ahi[mt], bhi[nt]);
                    mma_tf32(c[mt][nt], ahi[mt], blo[nt]);
                    mma_tf32(c[mt][nt], alo[mt], bhi[nt]);
                }
        }
        __syncthreads();
    }

#pragma unroll
    for (int mt = 0; mt < 2; mt++)
#pragma unroll
        for (int nt = 0; nt < 4; nt++)
#pragma unroll
            for (int hr = 0; hr < 2; hr++) {
                int row = m0 + wm0 + mt * 16 + g + hr * 8;
                if (row >= M) continue;
                int col = n0 + wn0 + nt * 8 + tg * 2;
                float v0 = c[mt][nt][hr * 2 + 0];
                float v1 = c[mt][nt][hr * 2 + 1];
                if (col < N1) {
                    if (bias) { v0 += bias[col]; v1 += bias[col + 1]; }
                    *(float2*)&C1[(size_t)row * N1 + col] = make_float2(v0, v1);
                } else {
                    *(float2*)&C2[(size_t)row * DD + (col - N1)] = make_float2(v0, v1);
                }
            }
}

// fused: [gh | m] = h @ [Whh^T | Ws]
__global__ __launch_bounds__(256) void gemm1_kernel(const float* __restrict__ bhh, int l, int M) {
    gemm_tf32_body(d_h, d_wB1 + (size_t)l * 512 * DD, bhh, d_gh, 384, d_m, M);
}
// gi = agg @ Wih^T + bih   (Wih already [384,128] row-major = B[n][k])
__global__ __launch_bounds__(256) void gemm2_kernel(const float* __restrict__ Wih,
                                                    const float* __restrict__ bih, int M) {
    gemm_tf32_body(d_agg, Wih, bih, d_gi, 384, nullptr, M);
}

// ---------------- fused GRU gates + ReLU ---------------------------------------
__global__ void gru_kernel(int n_nodes) {
    int idx = blockIdx.x * blockDim.x + threadIdx.x;
    if (idx >= n_nodes * DD) return;
    int i = idx / DD, j = idx % DD;
    const float* gir = d_gi + (size_t)i * 3 * DD;
    const float* ghr = d_gh + (size_t)i * 3 * DD;
    float ir = gir[j], iz = gir[DD + j], in_ = gir[2 * DD + j];
    float hr = ghr[j], hz = ghr[DD + j], hn = ghr[2 * DD + j];
    float r = 1.f / (1.f + expf(-(ir + hr)));
    float z = 1.f / (1.f + expf(-(iz + hz)));
    float nn = tanhf(in_ + r * hn);
    float hv = d_h[idx];
    d_h[idx] = fmaxf((1.f - z) * nn + z * hv, 0.f);
}

// ---------------- mean pool -----------------------------------------------------
__global__ void pool_kernel(const void* __restrict__ batch, int n_nodes) {
    int idx = blockIdx.x * blockDim.x + threadIdx.x;
    if (idx >= n_nodes * DD) return;
    int i = idx / DD, j = idx % DD;
    int g = load_idx(batch, i);
    if (g < 0 || g >= NGRAPHS) return;
    atomicAdd(&d_pool[g * DD + j], d_h[idx]);
    if (j == 0) atomicAdd(&d_gcnt[g], 1.f);
}

// ---------------- readout FC1(elu) + FC2 ----------------------------------------
__global__ void readout_kernel(const float* __restrict__ fc1w, const float* __restrict__ fc1b,
                               const float* __restrict__ fc2w, const float* __restrict__ fc2b) {
    int g = blockIdx.x;
    int j = threadIdx.x;
    __shared__ float hg[DD];
    __shared__ float h2[DD];
    float c = fmaxf(d_gcnt[g], 1.f);
    hg[j] = d_pool[g * DD + j] / c;
    __syncthreads();
    float a = fc1b[j];
#pragma unroll 4
    for (int k = 0; k < DD; k++) a += hg[k] * fc1w[j * DD + k];
    h2[j] = (a > 0.f) ? a : expm1f(a);
    __syncthreads();
    if (j < NCLASSES) {
        float s = fc2b[j];
#pragma unroll 4
        for (int k = 0; k < DD; k++) s += h2[k] * fc2w[j * DD + k];
        d_logits[g * NCLASSES + j] = s;
    }
}

// ---------------- log_softmax over axis 0 ---------------------------------------
__global__ void lsm_kernel(float* __restrict__ out) {
    int c = blockIdx.x;
    int g = threadIdx.x;
    __shared__ float sh[NGRAPHS];
    float x = d_logits[g * NCLASSES + c];
    sh[g] = x;
    __syncthreads();
    for (int off = NGRAPHS / 2; off > 0; off >>= 1) {
        if (g < off) sh[g] = fmaxf(sh[g], sh[g + off]);
        __syncthreads();
    }
    float mx = sh[0];
    __syncthreads();
    sh[g] = expf(x - mx);
    __syncthreads();
    for (int off = NGRAPHS / 2; off > 0; off >>= 1) {
        if (g < off) sh[g] += sh[g + off];
        __syncthreads();
    }
    float lse = mx + logf(sh[0]);
    out[g * NCLASSES + c] = x - lse;
}

// ---------------- launch ---------------------------------------------------------
extern "C" void kernel_launch(void* const* d_in, const int* in_sizes, int n_in,
                              void* d_out, int out_size) {
    const float* h_in  = (const float*)d_in[0];
    const void*  ei    = d_in[1];
    const void*  batch = d_in[3];
    const float* Ws   = (const float*)d_in[4];
    const float* Wih  = (const float*)d_in[5];
    const float* Whh  = (const float*)d_in[6];
    const float* bih  = (const float*)d_in[7];
    const float* bhh  = (const float*)d_in[8];
    const float* fc1w = (const float*)d_in[9];
    const float* fc1b = (const float*)d_in[10];
    const float* fc2w = (const float*)d_in[11];
    const float* fc2b = (const float*)d_in[12];
    float* out = (float*)d_out;

    int n_nodes = in_sizes[0] / DD;
    int n_edges = in_sizes[1] / 2;
    int nh = n_nodes * DD;

    detect_kernel<<<1, 128>>>(ei);
    copy_h_kernel<<<(nh + 255) / 256, 256>>>(h_in, nh);
    conv_wB1_kernel<<<(NLAYERS * 512 * DD + 255) / 256, 256>>>(Whh, Ws);

    // CSC build (once; reused across layers)
    zero_cnt_kernel<<<(n_nodes + 255) / 256, 256>>>(n_nodes);
    count_kernel<<<(n_edges + 255) / 256, 256>>>(ei, n_edges);
    scan_kernel<<<1, 1024>>>(n_nodes);
    zero_cnt_kernel<<<(n_nodes + 255) / 256, 256>>>(n_nodes);
    fill_kernel<<<(n_edges + 255) / 256, 256>>>(ei, n_edges);

    dim3 grid1((n_nodes + 127) / 128, 8);   // 512 output cols: [gh(384) | m(128)]
    dim3 grid2((n_nodes + 127) / 128, 6);   // 384 output cols: gi

    for (int l = 0; l < NLAYERS; l++) {
        gemm1_kernel<<<grid1, 256>>>(bhh + (size_t)l * 3 * DD, l, n_nodes);
        agg_kernel<<<(n_nodes * 32 + 255) / 256, 256>>>(n_nodes);
        gemm2_kernel<<<grid2, 256>>>(Wih + (size_t)l * 384 * DD, bih + (size_t)l * 3 * DD, n_nodes);
        gru_kernel<<<(nh + 255) / 256, 256>>>(n_nodes);
    }

    zero_pool_kernel<<<(NGRAPHS * DD + 255) / 256, 256>>>();
    pool_kernel<<<(nh + 255) / 256, 256>>>(batch, n_nodes);
    readout_kernel<<<NGRAPHS, DD>>>(fc1w, fc1b, fc2w, fc2b);
    lsm_kernel<<<NCLASSES, NGRAPHS>>>(out);
}

// round 11
// speedup vs baseline: 1.2539x; 1.1562x over previous
#include <cuda_runtime.h>
#include <math.h>
#include <stdint.h>

#define NNODES 50000
#define NEDGES 600000
#define DD 128
#define NGRAPHS 512
#define NCLASSES 10
#define NLAYERS 4

// ---------------- scratch (static device globals) ---------------------------
__device__ float d_h[NNODES * DD];
__device__ float d_m[NNODES * DD];
__device__ float d_agg[NNODES * DD];
__device__ float d_gi[NNODES * 3 * DD];
__device__ float d_gh[NNODES * 3 * DD];
__device__ float d_wB1[NLAYERS * 512 * DD];   // [Whh(384) ; Ws^T(128)] per layer
__device__ int   d_off[NNODES + 1];
__device__ int   d_cnt[NNODES];
__device__ int   d_csc[NEDGES];
__device__ float d_pool[NGRAPHS * DD];
__device__ float d_gcnt[NGRAPHS];
__device__ float d_logits[NGRAPHS * NCLASSES];
__device__ int   d_is64;

// ---------------- tf32 helpers ------------------------------------------------
__device__ __forceinline__ uint32_t f2tf32(float x) {
    uint32_t r;
    asm("cvt.rna.tf32.f32 %0, %1;" : "=r"(r) : "f"(x));
    return r;
}
__device__ __forceinline__ float rna(float x) {
    return __uint_as_float(f2tf32(x));
}
__device__ __forceinline__ void split2(float x, float& hi, float& lo) {
    uint32_t h = f2tf32(x);
    hi = __uint_as_float(h);
    lo = __uint_as_float(f2tf32(x - __uint_as_float(h)));
}
__device__ __forceinline__ void mma_tf32(float* c, const uint32_t* a, const uint32_t* b) {
    asm volatile(
        "mma.sync.aligned.m16n8k8.row.col.f32.tf32.tf32.f32 "
        "{%0,%1,%2,%3},{%4,%5,%6,%7},{%8,%9},{%0,%1,%2,%3};"
        : "+f"(c[0]), "+f"(c[1]), "+f"(c[2]), "+f"(c[3])
        : "r"(a[0]), "r"(a[1]), "r"(a[2]), "r"(a[3]), "r"(b[0]), "r"(b[1]));
}

// ---------------- index dtype detection ---------------------------------------
__global__ void detect_kernel(const void* __restrict__ ei) {
    __shared__ int nz;
    if (threadIdx.x == 0) nz = 0;
    __syncthreads();
    const int* w = (const int*)ei;
    int v = w[2 * threadIdx.x + 1];
    if (v != 0) atomicAdd(&nz, 1);
    __syncthreads();
    if (threadIdx.x == 0) d_is64 = (nz == 0) ? 1 : 0;
}
__device__ __forceinline__ int load_idx(const void* p, int i) {
    return d_is64 ? (int)((const long long*)p)[i] : ((const int*)p)[i];
}

// ---------------- utility kernels ---------------------------------------------
__global__ void copy_h_kernel(const float* __restrict__ src, int n) {
    int i = blockIdx.x * blockDim.x + threadIdx.x;
    if (i < n) d_h[i] = src[i];
}
__global__ void zero_cnt_kernel(int n) {
    int i = blockIdx.x * blockDim.x + threadIdx.x;
    if (i < n) d_cnt[i] = 0;
}
__global__ void zero_pool_kernel() {
    int i = blockIdx.x * blockDim.x + threadIdx.x;
    if (i < NGRAPHS * DD) d_pool[i] = 0.f;
    if (i < NGRAPHS) d_gcnt[i] = 0.f;
}
// B1 = [Whh (rows 0..383) ; Ws^T (rows 384..511)] per layer, fp32
__global__ void conv_wB1_kernel(const float* __restrict__ Whh, const float* __restrict__ Ws) {
    int i = blockIdx.x * blockDim.x + threadIdx.x;
    if (i >= NLAYERS * 512 * DD) return;
    int l = i / (512 * DD);
    int r = (i / DD) % 512;
    int k = i % DD;
    d_wB1[i] = (r < 384) ? Whh[(size_t)l * 384 * DD + r * DD + k]
                         : Ws[(size_t)l * DD * DD + k * DD + (r - 384)];
}

// ---------------- CSC build ----------------------------------------------------
__global__ void count_kernel(const void* __restrict__ ei, int n_edges) {
    int e = blockIdx.x * blockDim.x + threadIdx.x;
    if (e >= n_edges) return;
    int dst = load_idx(ei, n_edges + e);
    if (dst >= 0 && dst < NNODES) atomicAdd(&d_cnt[dst], 1);
}
__global__ void scan_kernel(int n) {
    __shared__ int tmp[1024];
    __shared__ int carry;
    int tid = threadIdx.x;
    if (tid == 0) carry = 0;
    __syncthreads();
    for (int base = 0; base < n; base += 1024) {
        int v = (base + tid < n) ? d_cnt[base + tid] : 0;
        tmp[tid] = v;
        __syncthreads();
        for (int off = 1; off < 1024; off <<= 1) {
            int t = (tid >= off) ? tmp[tid - off] : 0;
            __syncthreads();
            tmp[tid] += t;
            __syncthreads();
        }
        int excl = tmp[tid] - v;
        if (base + tid < n) d_off[base + tid] = carry + excl;
        __syncthreads();
        if (tid == 1023) carry += tmp[1023];
        __syncthreads();
    }
    if (tid == 0) d_off[n] = carry;
}
__global__ void fill_kernel(const void* __restrict__ ei, int n_edges) {
    int e = blockIdx.x * blockDim.x + threadIdx.x;
    if (e >= n_edges) return;
    int dst = load_idx(ei, n_edges + e);
    int src = load_idx(ei, e);
    if (dst < 0 || dst >= NNODES || src < 0 || src >= NNODES) return;
    int pos = d_off[dst] + atomicAdd(&d_cnt[dst], 1);
    if (pos < NEDGES) d_csc[pos] = src;
}

// ---------------- aggregation: one warp per node, float4 per lane --------------
__global__ void agg_kernel(int n_nodes) {
    int warp = (blockIdx.x * blockDim.x + threadIdx.x) >> 5;
    int lane = threadIdx.x & 31;
    if (warp >= n_nodes) return;
    int s = d_off[warp], e = d_off[warp + 1];
    float4 acc = make_float4(0.f, 0.f, 0.f, 0.f);
    for (int i = s; i < e; i++) {
        int src = d_csc[i];
        float4 v = *(const float4*)(d_m + (size_t)src * DD + lane * 4);
        acc.x += v.x; acc.y += v.y; acc.z += v.z; acc.w += v.w;
    }
    *(float4*)(d_agg + (size_t)warp * DD + lane * 4) = acc;
}

// ---------------- tf32x2 GEMM: A rounded once, B split hi/lo -------------------
// Double-buffered BK=16 pipeline with register prefetch; one sync per chunk.
// C[M,:] = A[M,128] @ B[N,128]^T (+bias); cols < N1 -> C1, else C2 (stride 128).
#define SW 20   // padded row width; (20g+tg) mod 32 conflict-free
__device__ __forceinline__ void gemm_tf32_body(
    const float* __restrict__ A, const float* __restrict__ B,
    const float* __restrict__ bias, float* __restrict__ C1, int N1,
    float* __restrict__ C2, int M)
{
    __shared__ float sAh[2][128][SW];
    __shared__ float sBh[2][64][SW], sBl[2][64][SW];
    int tid = threadIdx.x, lane = tid & 31, wid = tid >> 5;
    int g = lane >> 2, tg = lane & 3;
    int m0 = blockIdx.x * 128, n0 = blockIdx.y * 64;
    int wm0 = (wid & 3) * 32, wn0 = (wid >> 2) * 32;

    // staging coordinates (fixed per thread)
    int ar0 = tid >> 2, aq = tid & 3;        // A rows: ar0 and ar0+64... (t*64 offset via ch)
    int br = tid >> 2, bq = tid & 3;         // B row/quad

    float c[2][4][4] = {};
    float4 pa[2], pb;

    // prefetch chunk 0
    {
#pragma unroll
        for (int t = 0; t < 2; t++) {
            int row = ((tid + t * 256) >> 2);
            int q = (tid + t * 256) & 3;
            int gr = m0 + row;
            pa[t] = (gr < M) ? *(const float4*)&A[(size_t)gr * 128 + q * 4]
                             : make_float4(0.f, 0.f, 0.f, 0.f);
        }
        pb = *(const float4*)&B[(size_t)(n0 + br) * 128 + bq * 4];
    }

    int p = 0;
    for (int kc = 0; kc < 8; kc++) {
        // store staged chunk (A: single tf32 round; B: hi/lo split)
#pragma unroll
        for (int t = 0; t < 2; t++) {
            int row = ((tid + t * 256) >> 2);
            int q = (tid + t * 256) & 3;
            sAh[p][row][q * 4 + 0] = rna(pa[t].x);
            sAh[p][row][q * 4 + 1] = rna(pa[t].y);
            sAh[p][row][q * 4 + 2] = rna(pa[t].z);
            sAh[p][row][q * 4 + 3] = rna(pa[t].w);
        }
        {
            float4 hi, lo;
            split2(pb.x, hi.x, lo.x);
            split2(pb.y, hi.y, lo.y);
            split2(pb.z, hi.z, lo.z);
            split2(pb.w, hi.w, lo.w);
            *(float4*)&sBh[p][br][bq * 4] = hi;
            *(float4*)&sBl[p][br][bq * 4] = lo;
        }
        __syncthreads();

        // prefetch next chunk (LDG in flight during MMAs)
        if (kc < 7) {
            int k0 = (kc + 1) * 16;
#pragma unroll
            for (int t = 0; t < 2; t++) {
                int row = ((tid + t * 256) >> 2);
                int q = (tid + t * 256) & 3;
                int gr = m0 + row;
                pa[t] = (gr < M) ? *(const float4*)&A[(size_t)gr * 128 + k0 + q * 4]
                                 : make_float4(0.f, 0.f, 0.f, 0.f);
            }
            pb = *(const float4*)&B[(size_t)(n0 + br) * 128 + k0 + bq * 4];
        }

#pragma unroll
        for (int ks = 0; ks < 16; ks += 8) {
            // m16n8k8 tf32 fragments:
            //  a0=A[g][tg] a1=A[g+8][tg] a2=A[g][tg+4] a3=A[g+8][tg+4]
            //  b0=B[tg][g] b1=B[tg+4][g]  (B stored [n][k])
            uint32_t ah[2][4], bhi[4][2], blo[4][2];
#pragma unroll
            for (int mt = 0; mt < 2; mt++) {
                int r0 = wm0 + mt * 16 + g;
                ah[mt][0] = __float_as_uint(sAh[p][r0][ks + tg]);
                ah[mt][1] = __float_as_uint(sAh[p][r0 + 8][ks + tg]);
                ah[mt][2] = __float_as_uint(sAh[p][r0][ks + tg + 4]);
                ah[mt][3] = __float_as_uint(sAh[p][r0 + 8][ks + tg + 4]);
            }
#pragma unroll
            for (int nt = 0; nt < 4; nt++) {
                int r = wn0 + nt * 8 + g;
                bhi[nt][0] = __float_as_uint(sBh[p][r][ks + tg]);
                bhi[nt][1] = __float_as_uint(sBh[p][r][ks + tg + 4]);
                blo[nt][0] = __float_as_uint(sBl[p][r][ks + tg]);
                blo[nt][1] = __float_as_uint(sBl[p][r][ks + tg + 4]);
            }
#pragma unroll
            for (int mt = 0; mt < 2; mt++)
#pragma unroll
                for (int nt = 0; nt < 4; nt++) {
                    mma_tf32(c[mt][nt], ah[mt], bhi[nt]);
                    mma_tf32(c[mt][nt], ah[mt], blo[nt]);
                }
        }
        p ^= 1;
    }

#pragma unroll
    for (int mt = 0; mt < 2; mt++)
#pragma unroll
        for (int nt = 0; nt < 4; nt++)
#pragma unroll
            for (int hr = 0; hr < 2; hr++) {
                int row = m0 + wm0 + mt * 16 + g + hr * 8;
                if (row >= M) continue;
                int col = n0 + wn0 + nt * 8 + tg * 2;
                float v0 = c[mt][nt][hr * 2 + 0];
                float v1 = c[mt][nt][hr * 2 + 1];
                if (col < N1) {
                    if (bias) { v0 += bias[col]; v1 += bias[col + 1]; }
                    *(float2*)&C1[(size_t)row * N1 + col] = make_float2(v0, v1);
                } else {
                    *(float2*)&C2[(size_t)row * DD + (col - N1)] = make_float2(v0, v1);
                }
            }
}

// fused: [gh | m] = h @ [Whh^T | Ws]
__global__ __launch_bounds__(256) void gemm1_kernel(const float* __restrict__ bhh, int l, int M) {
    gemm_tf32_body(d_h, d_wB1 + (size_t)l * 512 * DD, bhh, d_gh, 384, d_m, M);
}
// gi = agg @ Wih^T + bih   (Wih already [384,128] row-major = B[n][k])
__global__ __launch_bounds__(256) void gemm2_kernel(const float* __restrict__ Wih,
                                                    const float* __restrict__ bih, int M) {
    gemm_tf32_body(d_agg, Wih, bih, d_gi, 384, nullptr, M);
}

// ---------------- fused GRU gates + ReLU ---------------------------------------
__global__ void gru_kernel(int n_nodes) {
    int idx = blockIdx.x * blockDim.x + threadIdx.x;
    if (idx >= n_nodes * DD) return;
    int i = idx / DD, j = idx % DD;
    const float* gir = d_gi + (size_t)i * 3 * DD;
    const float* ghr = d_gh + (size_t)i * 3 * DD;
    float ir = gir[j], iz = gir[DD + j], in_ = gir[2 * DD + j];
    float hr = ghr[j], hz = ghr[DD + j], hn = ghr[2 * DD + j];
    float r = 1.f / (1.f + expf(-(ir + hr)));
    float z = 1.f / (1.f + expf(-(iz + hz)));
    float nn = tanhf(in_ + r * hn);
    float hv = d_h[idx];
    d_h[idx] = fmaxf((1.f - z) * nn + z * hv, 0.f);
}

// ---------------- mean pool -----------------------------------------------------
__global__ void pool_kernel(const void* __restrict__ batch, int n_nodes) {
    int idx = blockIdx.x * blockDim.x + threadIdx.x;
    if (idx >= n_nodes * DD) return;
    int i = idx / DD, j = idx % DD;
    int g = load_idx(batch, i);
    if (g < 0 || g >= NGRAPHS) return;
    atomicAdd(&d_pool[g * DD + j], d_h[idx]);
    if (j == 0) atomicAdd(&d_gcnt[g], 1.f);
}

// ---------------- readout FC1(elu) + FC2 ----------------------------------------
__global__ void readout_kernel(const float* __restrict__ fc1w, const float* __restrict__ fc1b,
                               const float* __restrict__ fc2w, const float* __restrict__ fc2b) {
    int g = blockIdx.x;
    int j = threadIdx.x;
    __shared__ float hg[DD];
    __shared__ float h2[DD];
    float c = fmaxf(d_gcnt[g], 1.f);
    hg[j] = d_pool[g * DD + j] / c;
    __syncthreads();
    float a = fc1b[j];
#pragma unroll 4
    for (int k = 0; k < DD; k++) a += hg[k] * fc1w[j * DD + k];
    h2[j] = (a > 0.f) ? a : expm1f(a);
    __syncthreads();
    if (j < NCLASSES) {
        float s = fc2b[j];
#pragma unroll 4
        for (int k = 0; k < DD; k++) s += h2[k] * fc2w[j * DD + k];
        d_logits[g * NCLASSES + j] = s;
    }
}

// ---------------- log_softmax over axis 0 ---------------------------------------
__global__ void lsm_kernel(float* __restrict__ out) {
    int c = blockIdx.x;
    int g = threadIdx.x;
    __shared__ float sh[NGRAPHS];
    float x = d_logits[g * NCLASSES + c];
    sh[g] = x;
    __syncthreads();
    for (int off = NGRAPHS / 2; off > 0; off >>= 1) {
        if (g < off) sh[g] = fmaxf(sh[g], sh[g + off]);
        __syncthreads();
    }
    float mx = sh[0];
    __syncthreads();
    sh[g] = expf(x - mx);
    __syncthreads();
    for (int off = NGRAPHS / 2; off > 0; off >>= 1) {
        if (g < off) sh[g] += sh[g + off];
        __syncthreads();
    }
    float lse = mx + logf(sh[0]);
    out[g * NCLASSES + c] = x - lse;
}

// ---------------- launch ---------------------------------------------------------
extern "C" void kernel_launch(void* const* d_in, const int* in_sizes, int n_in,
                              void* d_out, int out_size) {
    const float* h_in  = (const float*)d_in[0];
    const void*  ei    = d_in[1];
    const void*  batch = d_in[3];
    const float* Ws   = (const float*)d_in[4];
    const float* Wih  = (const float*)d_in[5];
    const float* Whh  = (const float*)d_in[6];
    const float* bih  = (const float*)d_in[7];
    const float* bhh  = (const float*)d_in[8];
    const float* fc1w = (const float*)d_in[9];
    const float* fc1b = (const float*)d_in[10];
    const float* fc2w = (const float*)d_in[11];
    const float* fc2b = (const float*)d_in[12];
    float* out = (float*)d_out;

    int n_nodes = in_sizes[0] / DD;
    int n_edges = in_sizes[1] / 2;
    int nh = n_nodes * DD;

    detect_kernel<<<1, 128>>>(ei);
    copy_h_kernel<<<(nh + 255) / 256, 256>>>(h_in, nh);
    conv_wB1_kernel<<<(NLAYERS * 512 * DD + 255) / 256, 256>>>(Whh, Ws);

    // CSC build (once; reused across layers)
    zero_cnt_kernel<<<(n_nodes + 255) / 256, 256>>>(n_nodes);
    count_kernel<<<(n_edges + 255) / 256, 256>>>(ei, n_edges);
    scan_kernel<<<1, 1024>>>(n_nodes);
    zero_cnt_kernel<<<(n_nodes + 255) / 256, 256>>>(n_nodes);
    fill_kernel<<<(n_edges + 255) / 256, 256>>>(ei, n_edges);

    dim3 grid1((n_nodes + 127) / 128, 8);   // 512 output cols: [gh(384) | m(128)]
    dim3 grid2((n_nodes + 127) / 128, 6);   // 384 output cols: gi

    for (int l = 0; l < NLAYERS; l++) {
        gemm1_kernel<<<grid1, 256>>>(bhh + (size_t)l * 3 * DD, l, n_nodes);
        agg_kernel<<<(n_nodes * 32 + 255) / 256, 256>>>(n_nodes);
        gemm2_kernel<<<grid2, 256>>>(Wih + (size_t)l * 384 * DD, bih + (size_t)l * 3 * DD, n_nodes);
        gru_kernel<<<(nh + 255) / 256, 256>>>(n_nodes);
    }

    zero_pool_kernel<<<(NGRAPHS * DD + 255) / 256, 256>>>();
    pool_kernel<<<(nh + 255) / 256, 256>>>(batch, n_nodes);
    readout_kernel<<<NGRAPHS, DD>>>(fc1w, fc1b, fc2w, fc2b);
    lsm_kernel<<<NCLASSES, NGRAPHS>>>(out);
}